// round 7
// baseline (speedup 1.0000x reference)
#include <cuda_runtime.h>
#include <cstdint>

// Problem constants
#define Bn 4
#define Tn 64
#define Fn 32
#define Nn 512
#define Hn 64
#define SROWS 288
#define COLS_PER_CTA 16
#define CTAS_PER_B 32
#define NCTAS (Bn * CTAS_PER_B)   // 128 CTAs, 1/SM
#define NTHREADS 512
#define RPT 9

#define PITCH_V   388
#define NV        384
#define PITCH_YP  18
#define PITCH_SST 516             // S^T staging pitch (banks: 516%32=4 -> spread)

// smem layout (float offsets)
#define OFF_W      0                        // 64*384 = 24576
#define OFF_BIAS   24576                    // 64
#define OFF_SST    24640                    // 16*516 = 8256
#define OFF_YP     32896                    // 288*18 = 5184
#define OFF_V      38080                    // 16*388 = 6208
#define SMEM_FLOATS 44288
#define SMEM_BYTES  (SMEM_FLOATS * 4)       // 177152

// Persistent global state, plain row-major [288][512] per (buf,b)
__device__ __align__(16) float g_state[2][Bn][SROWS][Nn];
__device__ unsigned g_count = 0;
__device__ unsigned g_sense = 0;

__device__ __forceinline__ void grid_barrier(unsigned* lsense) {
    __syncthreads();
    if (threadIdx.x == 0) {
        __threadfence();                       // release + L1D invalidate path
        unsigned s = (*lsense) ^ 1u;
        *lsense = s;
        unsigned old = atomicAdd(&g_count, 1u);
        if (old == NCTAS - 1u) {
            atomicExch(&g_count, 0u);
            __threadfence();
            atomicExch(&g_sense, s);
        } else {
            while (atomicAdd(&g_sense, 0u) != s) { __nanosleep(64); }
            __threadfence();                   // acquire: CCTL.IVALL flushes L1D
        }
    }
    __syncthreads();
}

__device__ __forceinline__ unsigned long long ffma2(unsigned long long a,
                                                    unsigned long long b,
                                                    unsigned long long c) {
    unsigned long long d;
    asm("fma.rn.f32x2 %0, %1, %2, %3;" : "=l"(d) : "l"(a), "l"(b), "l"(c));
    return d;
}
__device__ __forceinline__ float upsum(unsigned long long p) {
    float lo, hi;
    asm("mov.b64 {%0, %1}, %2;" : "=f"(lo), "=f"(hi) : "l"(p));
    return lo + hi;
}

__global__ void __launch_bounds__(NTHREADS, 1)
hs_db_kernel(const float* __restrict__ x,      // (B,T,F,N)
             const float* __restrict__ z0,     // (B,H,N)
             const float* __restrict__ S,      // (B,T,1,N,N)
             const float* __restrict__ aW,     // (H,1,K,F)
             const float* __restrict__ bW,     // (H,1,K,H)
             const float* __restrict__ xBias,  // (H,1)
             const float* __restrict__ zBias,  // (H,1)
             float* __restrict__ out)          // (B,T,H,N)
{
    extern __shared__ float sm[];
    float* sW    = sm + OFF_W;
    float* sbias = sm + OFF_BIAS;
    float* sST   = sm + OFF_SST;   // [16][516]: S^T slice, col-major over k
    float* sYp   = sm + OFF_YP;
    float* sV    = sm + OFF_V;

    const int tid  = threadIdx.x;
    const int b    = blockIdx.x / CTAS_PER_B;
    const int col0 = (blockIdx.x % CTAS_PER_B) * COLS_PER_CTA;

    // phase-1 mapping: 2 k-groups of 256 threads; tile = 9 rows x 2 cols
    const int kg   = tid >> 8;            // 0/1: k in [256*kg, 256*kg+256)
    const int t256 = tid & 255;
    const int cgp  = t256 & 7;
    const int c0   = 2 * cgp;
    const int RG   = t256 >> 3;           // 0..31
    const int R0   = RG * RPT;
    const int kb   = 256 * kg;
    // x staging mapping
    const int mmA = tid >> 4;             // 0..31
    const int ccA = tid & 15;
    // phase-2 mapping
    const int hh  = tid >> 4;
    const int cc2 = tid & 15;

    // Load fused weights once
    for (int i = tid; i < Hn * 128; i += NTHREADS) {
        int h = i >> 7, j = i & 127;
        sW[h * NV + j] = aW[i];
    }
    for (int i = tid; i < Hn * 256; i += NTHREADS) {
        int h = i >> 8, j = i & 255;
        sW[h * NV + 128 + j] = bW[i];
    }
    if (tid < Hn) sbias[tid] = xBias[tid] + zBias[tid];

    // Init: zero this CTA's state columns; sV z-region <- z0
    for (int i = tid; i < SROWS * COLS_PER_CTA; i += NTHREADS) {
        int r = i >> 4, cc = i & 15;
        g_state[0][b][r][col0 + cc] = 0.0f;
    }
    for (int i = tid; i < Hn * COLS_PER_CTA; i += NTHREADS) {
        int g = i >> 4, cc = i & 15;
        sV[cc * PITCH_V + 128 + g] = z0[(b * Hn + g) * Nn + col0 + cc];
    }

    unsigned lsense = 0;
    grid_barrier(&lsense);   // barrier #1

    for (int t = 0; t < Tn; ++t) {
        const int cur = t & 1;
        const int nxt = cur ^ 1;
        const float* Sbt = S + (size_t)(b * Tn + t) * Nn * Nn;
        const float* xbt = x + (size_t)(b * Tn + t) * Fn * Nn;
        const float* gs  = &g_state[cur][b][0][0];

        // Stage x(t) -> sV[cc][0..31]
        sV[ccA * PITCH_V + mmA] = xbt[mmA * Nn + col0 + ccA];

        // Stage S(t) column slice transposed: sST[c][k] ; thread = one k-row
        {
            const float* srow = Sbt + (size_t)tid * Nn + col0;
            float4 v0 = *reinterpret_cast<const float4*>(srow);
            float4 v1 = *reinterpret_cast<const float4*>(srow + 4);
            float4 v2 = *reinterpret_cast<const float4*>(srow + 8);
            float4 v3 = *reinterpret_cast<const float4*>(srow + 12);
            float* d = sST + tid;
            d[0 * PITCH_SST]  = v0.x; d[1 * PITCH_SST]  = v0.y;
            d[2 * PITCH_SST]  = v0.z; d[3 * PITCH_SST]  = v0.w;
            d[4 * PITCH_SST]  = v1.x; d[5 * PITCH_SST]  = v1.y;
            d[6 * PITCH_SST]  = v1.z; d[7 * PITCH_SST]  = v1.w;
            d[8 * PITCH_SST]  = v2.x; d[9 * PITCH_SST]  = v2.y;
            d[10 * PITCH_SST] = v2.z; d[11 * PITCH_SST] = v2.w;
            d[12 * PITCH_SST] = v3.x; d[13 * PITCH_SST] = v3.y;
            d[14 * PITCH_SST] = v3.z; d[15 * PITCH_SST] = v3.w;
        }
        __syncthreads();

        // ---- Phase 1: barrier-free k-loop; state streamed via LDG from L2 ----
        unsigned long long acc[RPT][2];
#pragma unroll
        for (int r = 0; r < RPT; ++r) { acc[r][0] = 0ull; acc[r][1] = 0ull; }

        {
            const float* sstc0 = sST + c0 * PITCH_SST;
            const float* sstc1 = sstc0 + PITCH_SST;
            const float* gsr   = gs + (size_t)R0 * Nn + kb;
#pragma unroll 2
            for (int s = 0; s < 64; ++s) {
                const int k = 4 * s;
                const ulonglong2 b0 = *reinterpret_cast<const ulonglong2*>(sstc0 + kb + k);
                const ulonglong2 b1 = *reinterpret_cast<const ulonglong2*>(sstc1 + kb + k);
#pragma unroll
                for (int r = 0; r < RPT; ++r) {
                    const ulonglong2 sv = *reinterpret_cast<const ulonglong2*>(
                        gsr + (size_t)r * Nn + k);
                    acc[r][0] = ffma2(sv.x, b0.x, acc[r][0]);
                    acc[r][1] = ffma2(sv.x, b1.x, acc[r][1]);
                    acc[r][0] = ffma2(sv.y, b0.y, acc[r][0]);
                    acc[r][1] = ffma2(sv.y, b1.y, acc[r][1]);
                }
            }
        }

        // Reduce the two k-group partials; write Y into transposed sV
        __syncthreads();
        if (kg == 1) {
#pragma unroll
            for (int r = 0; r < RPT; ++r) {
                sYp[(R0 + r) * PITCH_YP + c0]     = upsum(acc[r][0]);
                sYp[(R0 + r) * PITCH_YP + c0 + 1] = upsum(acc[r][1]);
            }
        }
        __syncthreads();
        if (kg == 0) {
#pragma unroll
            for (int r = 0; r < RPT; ++r) {
                int row = R0 + r;
                int j = (row < 96) ? (32 + row) : (96 + row);
                sV[c0 * PITCH_V + j] =
                    upsum(acc[r][0]) + sYp[row * PITCH_YP + c0];
                sV[(c0 + 1) * PITCH_V + j] =
                    upsum(acc[r][1]) + sYp[row * PITCH_YP + c0 + 1];
            }
        }
        __syncthreads();

        // ---- Phase 2: pre[h,c] = bias[h] + sum_j sW[h][j] * sV[c][j] ----
        unsigned long long pa[2] = {0ull, 0ull};
        {
            const float* vp = sV + cc2 * PITCH_V;
#pragma unroll 4
            for (int j = 0; j < NV; j += 4) {
                ulonglong2 v = *reinterpret_cast<const ulonglong2*>(vp + j);
#pragma unroll
                for (int i = 0; i < 2; ++i) {
                    ulonglong2 w = *reinterpret_cast<const ulonglong2*>(
                        sW + (hh + 32 * i) * NV + j);
                    pa[i] = ffma2(w.x, v.x, pa[i]);
                    pa[i] = ffma2(w.y, v.y, pa[i]);
                }
            }
        }
        float zv[2];
#pragma unroll
        for (int i = 0; i < 2; ++i)
            zv[i] = tanhf(sbias[hh + 32 * i] + upsum(pa[i]));

        // ---- State shift for t+1 (column-local STG) ----
        //  rows 0..31   <- x(t)       (sV j=r)
        //  rows 32..95  <- Y[0..63]   (sV j=r)
        //  rows 96..159 <- z(t-1)     (sV j=r+32)
        //  rows 160..287<- Y[96..223] (sV j=r+32)
#pragma unroll
        for (int it = 0; it < 9; ++it) {
            int i = tid + it * NTHREADS;
            int r = i >> 4, cc = i & 15;
            int j = (r < 96) ? r : (r + 32);
            g_state[nxt][b][r][col0 + cc] = sV[cc * PITCH_V + j];
        }
        __syncthreads();   // all reads of z(t-1) from sV done before overwrite

        // write z(t) -> out + sV z-region
#pragma unroll
        for (int i = 0; i < 2; ++i) {
            int h = hh + 32 * i;
            out[(((size_t)b * Tn + t) * Hn + h) * Nn + col0 + cc2] = zv[i];
            sV[cc2 * PITCH_V + 128 + h] = zv[i];
        }

        grid_barrier(&lsense);   // barriers #2..#65
    }

    grid_barrier(&lsense);       // barrier #66 (even parity)
}

extern "C" void kernel_launch(void* const* d_in, const int* in_sizes, int n_in,
                              void* d_out, int out_size) {
    const float* x     = (const float*)d_in[0];
    const float* z0    = (const float*)d_in[1];
    const float* S     = (const float*)d_in[2];
    const float* aW    = (const float*)d_in[3];
    const float* bW    = (const float*)d_in[4];
    const float* xBias = (const float*)d_in[5];
    const float* zBias = (const float*)d_in[6];
    float* out = (float*)d_out;

    cudaFuncSetAttribute(hs_db_kernel,
                         cudaFuncAttributeMaxDynamicSharedMemorySize, SMEM_BYTES);
    hs_db_kernel<<<NCTAS, NTHREADS, SMEM_BYTES>>>(x, z0, S, aW, bW, xBias, zBias, out);
}

// round 8
// speedup vs baseline: 1.4088x; 1.4088x over previous
#include <cuda_runtime.h>
#include <cstdint>

// Problem constants
#define Bn 4
#define Tn 64
#define Fn 32
#define Nn 512
#define Hn 64
#define SROWS 288
#define COLS_PER_CTA 16
#define CTAS_PER_B 32
#define NCTAS (Bn * CTAS_PER_B)   // 128 CTAs, 1/SM
#define NTHREADS 256
#define MB 32                     // n-chunk width
#define NCHUNK (Nn / MB)          // 16
#define RPT 9

#define PITCH_SS 36
#define PITCH_V  388
#define NV       384
#define PITCH_YP 18

#define CHUNK_FLOATS (SROWS * MB)          // 9216
#define CHUNK_BYTES  (CHUNK_FLOATS * 4)    // 36864

// smem layout (float offsets)
#define OFF_W      0                        // 64*384 = 24576
#define OFF_BIAS   24576                    // 64
#define OFF_MBAR   24640                    // 4
#define OFF_STATE  24644                    // 2*9216 = 18432 (byte 98576, 16B aligned)
#define OFF_SS     43076                    // 2*576 = 1152
#define SS_BUF     (16 * PITCH_SS)          // 576
#define OFF_YP     44228                    // 288*18 = 5184
#define OFF_V      49412                    // 16*388 = 6208
#define SMEM_FLOATS 55620
#define SMEM_BYTES  (SMEM_FLOATS * 4)       // 222480

// Persistent global state, chunk-major, XOR-swizzled within each 32-float row:
// element (row, c) of a chunk lives at row*32 + (((c>>2)^(row&7))<<2 | (c&3))
__device__ __align__(16) float g_state[2][Bn][NCHUNK][SROWS][MB];
__device__ unsigned g_count = 0;
__device__ unsigned g_sense = 0;

__device__ __forceinline__ int swz(int r, int c32) {
    return r * 32 + (((((unsigned)c32 >> 2) ^ ((unsigned)r & 7u)) << 2) | (c32 & 3));
}

__device__ __forceinline__ void grid_barrier(unsigned* lsense) {
    __syncthreads();
    if (threadIdx.x == 0) {
        __threadfence();
        unsigned s = (*lsense) ^ 1u;
        *lsense = s;
        unsigned old = atomicAdd(&g_count, 1u);
        if (old == NCTAS - 1u) {
            atomicExch(&g_count, 0u);
            __threadfence();
            atomicExch(&g_sense, s);
        } else {
            while (atomicAdd(&g_sense, 0u) != s) { __nanosleep(64); }
            __threadfence();
        }
    }
    __syncthreads();
}

__device__ __forceinline__ unsigned long long ffma2(unsigned long long a,
                                                    unsigned long long b,
                                                    unsigned long long c) {
    unsigned long long d;
    asm("fma.rn.f32x2 %0, %1, %2, %3;" : "=l"(d) : "l"(a), "l"(b), "l"(c));
    return d;
}
__device__ __forceinline__ float upsum(unsigned long long p) {
    float lo, hi;
    asm("mov.b64 {%0, %1}, %2;" : "=f"(lo), "=f"(hi) : "l"(p));
    return lo + hi;
}

// mbarrier helpers
__device__ __forceinline__ void mbar_init(uint32_t addr, uint32_t count) {
    asm volatile("mbarrier.init.shared.b64 [%0], %1;" :: "r"(addr), "r"(count) : "memory");
}
__device__ __forceinline__ void mbar_expect_tx(uint32_t addr, uint32_t bytes) {
    asm volatile("mbarrier.arrive.expect_tx.shared.b64 _, [%0], %1;"
                 :: "r"(addr), "r"(bytes) : "memory");
}
__device__ __forceinline__ void mbar_wait(uint32_t addr, uint32_t parity) {
    uint32_t done;
    asm volatile(
        "{\n\t.reg .pred p;\n\t"
        "mbarrier.try_wait.parity.acquire.cta.shared::cta.b64 p, [%1], %2;\n\t"
        "selp.b32 %0, 1, 0, p;\n\t}"
        : "=r"(done) : "r"(addr), "r"(parity) : "memory");
    if (!done) {
        asm volatile(
            "{\n\t.reg .pred P1;\n\t"
            "WL_%=:\n\t"
            "mbarrier.try_wait.parity.acquire.cta.shared::cta.b64 P1, [%0], %1, 0x989680;\n\t"
            "@P1 bra.uni WD_%=;\n\t"
            "bra.uni WL_%=;\n\t"
            "WD_%=:\n\t}"
            :: "r"(addr), "r"(parity) : "memory");
    }
}
__device__ __forceinline__ void bulk_copy(uint32_t dst_smem, const void* src, uint32_t bytes,
                                          uint32_t mbar) {
    asm volatile(
        "cp.async.bulk.shared::cta.global.mbarrier::complete_tx::bytes [%0], [%1], %2, [%3];"
        :: "r"(dst_smem), "l"(src), "r"(bytes), "r"(mbar) : "memory");
}

__global__ void __launch_bounds__(NTHREADS, 1)
hs_db_kernel(const float* __restrict__ x,      // (B,T,F,N)
             const float* __restrict__ z0,     // (B,H,N)
             const float* __restrict__ S,      // (B,T,1,N,N)
             const float* __restrict__ aW,     // (H,1,K,F)
             const float* __restrict__ bW,     // (H,1,K,H)
             const float* __restrict__ xBias,  // (H,1)
             const float* __restrict__ zBias,  // (H,1)
             float* __restrict__ out)          // (B,T,H,N)
{
    extern __shared__ float sm[];
    float* sW    = sm + OFF_W;
    float* sbias = sm + OFF_BIAS;
    float* sYp   = sm + OFF_YP;
    float* sV    = sm + OFF_V;

    const int tid  = threadIdx.x;
    const int b    = blockIdx.x / CTAS_PER_B;
    const int col0 = (blockIdx.x % CTAS_PER_B) * COLS_PER_CTA;
    const int kc0  = col0 >> 5;
    const int cmb  = col0 & 31;

    // phase-1 mapping: 2 k-groups of 128 threads; tile = 9 rows x 4 cols
    // cols per thread: {cgp, cgp+4, cgp+8, cgp+12} (bank-friendly under pitch 36)
    const int kg   = tid >> 7;            // 0/1: n-range within chunk [16*kg,16*kg+16)
    const int t128 = tid & 127;
    const int cgp  = t128 & 3;
    const int RG   = t128 >> 2;           // 0..31
    const int R0   = RG * RPT;
    // S staging: two elements per thread
    const int klA = tid >> 4;             // 0..15
    const int ccA = tid & 15;
    // phase-2 mapping: thread -> (4 h, 1 col)
    const int hq  = tid >> 4;             // 0..15; h in {hq,hq+16,hq+32,hq+48}
    const int cc2 = tid & 15;

    const uint32_t smem_u32 = (uint32_t)__cvta_generic_to_shared(sm);
    const uint32_t mbar0 = smem_u32 + OFF_MBAR * 4;
    const uint32_t mbar1 = mbar0 + 8;
    const uint32_t st_smem0 = smem_u32 + OFF_STATE * 4;
    const uint32_t st_smem1 = st_smem0 + CHUNK_BYTES;

    if (tid == 0) { mbar_init(mbar0, 1); mbar_init(mbar1, 1); }

    // per-thread constant row swizzle keys and row offsets
    int xr[RPT], roff[RPT];
#pragma unroll
    for (int r = 0; r < RPT; ++r) {
        xr[r]   = (RG + r) & 7;
        roff[r] = (R0 + r) * 32;
    }

    // Load fused weights
    for (int i = tid; i < Hn * 128; i += NTHREADS) {
        int h = i >> 7, j = i & 127;
        sW[h * NV + j] = aW[i];
    }
    for (int i = tid; i < Hn * 256; i += NTHREADS) {
        int h = i >> 8, j = i & 255;
        sW[h * NV + 128 + j] = bW[i];
    }
    if (tid < Hn) sbias[tid] = xBias[tid] + zBias[tid];

    // Init: zero this CTA's swizzled state columns; sV z-region <- z0
    for (int i = tid; i < SROWS * COLS_PER_CTA; i += NTHREADS) {
        int r = i >> 4, cc = i & 15;
        g_state[0][b][kc0][0][swz(r, cmb + cc)] = 0.0f;
    }
    for (int i = tid; i < Hn * COLS_PER_CTA; i += NTHREADS) {
        int g = i >> 4, cc = i & 15;
        sV[cc * PITCH_V + 128 + g] = z0[(b * Hn + g) * Nn + col0 + cc];
    }

    unsigned lsense = 0;
    unsigned ph0 = 0, ph1 = 0;
    grid_barrier(&lsense);   // barrier #1

    for (int t = 0; t < Tn; ++t) {
        const int cur = t & 1;
        const int nxt = cur ^ 1;
        const float* Sbt = S + (size_t)(b * Tn + t) * Nn * Nn;
        const float* xbt = x + (size_t)(b * Tn + t) * Fn * Nn;
        const float* gst = &g_state[cur][b][0][0][0];

        // Stage x(t) -> sV[cc][0..31]
        sV[ccA * PITCH_V + klA]      = xbt[klA * Nn + col0 + ccA];
        sV[ccA * PITCH_V + 16 + klA] = xbt[(16 + klA) * Nn + col0 + ccA];

        // prologue: chunk 0
        if (tid == 0) {
            mbar_expect_tx(mbar0, CHUNK_BYTES);
            bulk_copy(st_smem0, gst, CHUNK_BYTES, mbar0);
        }
        float sA0 = Sbt[(size_t)klA * Nn + col0 + ccA];
        float sA1 = Sbt[(size_t)(16 + klA) * Nn + col0 + ccA];
        {
            float* ss0 = sm + OFF_SS;
            ss0[ccA * PITCH_SS + klA]      = sA0;
            ss0[ccA * PITCH_SS + 16 + klA] = sA1;
        }
        __syncthreads();
        mbar_wait(mbar0, ph0); ph0 ^= 1u;

        unsigned long long acc[RPT][4];
#pragma unroll
        for (int r = 0; r < RPT; ++r)
#pragma unroll
            for (int ci = 0; ci < 4; ++ci) acc[r][ci] = 0ull;

        for (int k = 0; k < NCHUNK; ++k) {
            const int buf = k & 1, nb = buf ^ 1;
            // prefetch chunk k+1
            if (k < NCHUNK - 1) {
                const int m1 = (k + 1) * MB;
                sA0 = Sbt[(size_t)(m1 + klA) * Nn + col0 + ccA];
                sA1 = Sbt[(size_t)(m1 + 16 + klA) * Nn + col0 + ccA];
                if (tid == 0) {
                    uint32_t mb = nb ? mbar1 : mbar0;
                    uint32_t ds = nb ? st_smem1 : st_smem0;
                    mbar_expect_tx(mb, CHUNK_BYTES);
                    bulk_copy(ds, gst + (size_t)(k + 1) * CHUNK_FLOATS, CHUNK_BYTES, mb);
                }
            }
            // compute this k-group's half of the chunk
            {
                const float* stb = sm + OFF_STATE + buf * CHUNK_FLOATS;
                const float* ssb = sm + OFF_SS + buf * SS_BUF;
#pragma unroll
                for (int s = 0; s < 4; ++s) {
                    const int kloc = 16 * kg + 4 * s;
                    const int seg  = 4 * kg + s;
                    ulonglong2 bb[4];
#pragma unroll
                    for (int ci = 0; ci < 4; ++ci)
                        bb[ci] = *reinterpret_cast<const ulonglong2*>(
                            ssb + (cgp + 4 * ci) * PITCH_SS + kloc);
#pragma unroll
                    for (int r = 0; r < RPT; ++r) {
                        const ulonglong2 sv = *reinterpret_cast<const ulonglong2*>(
                            stb + roff[r] + ((seg ^ xr[r]) << 2));
#pragma unroll
                        for (int ci = 0; ci < 4; ++ci) {
                            acc[r][ci] = ffma2(sv.x, bb[ci].x, acc[r][ci]);
                            acc[r][ci] = ffma2(sv.y, bb[ci].y, acc[r][ci]);
                        }
                    }
                }
            }
            if (k < NCHUNK - 1) {
                __syncthreads();     // all reads of ss[nb] (chunk k-1) done
                float* ssn = sm + OFF_SS + nb * SS_BUF;
                ssn[ccA * PITCH_SS + klA]      = sA0;
                ssn[ccA * PITCH_SS + 16 + klA] = sA1;
                __syncthreads();
                if (nb) { mbar_wait(mbar1, ph1); ph1 ^= 1u; }
                else    { mbar_wait(mbar0, ph0); ph0 ^= 1u; }
            }
        }

        // Reduce the two k-group partials; write Y into transposed sV
        __syncthreads();
        if (kg == 1) {
#pragma unroll
            for (int r = 0; r < RPT; ++r)
#pragma unroll
                for (int ci = 0; ci < 4; ++ci)
                    sYp[(R0 + r) * PITCH_YP + cgp + 4 * ci] = upsum(acc[r][ci]);
        }
        __syncthreads();
        if (kg == 0) {
#pragma unroll
            for (int r = 0; r < RPT; ++r) {
                int row = R0 + r;
                int j = (row < 96) ? (32 + row) : (96 + row);
#pragma unroll
                for (int ci = 0; ci < 4; ++ci) {
                    int c = cgp + 4 * ci;
                    sV[c * PITCH_V + j] =
                        upsum(acc[r][ci]) + sYp[row * PITCH_YP + c];
                }
            }
        }
        __syncthreads();

        // Phase 2: pre[h,c] = bias[h] + sum_j sW[h][j] * sV[c][j]
        unsigned long long pa[4] = {0ull, 0ull, 0ull, 0ull};
        {
            const float* vp = sV + cc2 * PITCH_V;
#pragma unroll 4
            for (int j = 0; j < NV; j += 4) {
                ulonglong2 v = *reinterpret_cast<const ulonglong2*>(vp + j);
#pragma unroll
                for (int i = 0; i < 4; ++i) {
                    ulonglong2 w = *reinterpret_cast<const ulonglong2*>(
                        sW + (hq + 16 * i) * NV + j);
                    pa[i] = ffma2(w.x, v.x, pa[i]);
                    pa[i] = ffma2(w.y, v.y, pa[i]);
                }
            }
        }
        float zv[4];
#pragma unroll
        for (int i = 0; i < 4; ++i)
            zv[i] = tanhf(sbias[hq + 16 * i] + upsum(pa[i]));

        // State shift for t+1 (swizzled global writes, column-local)
        float* gnxt = &g_state[nxt][b][kc0][0][0];
#pragma unroll
        for (int it = 0; it < 18; ++it) {
            int i = tid + it * NTHREADS;
            int r = i >> 4, cc = i & 15;
            int j = (r < 96) ? r : (r + 32);
            gnxt[swz(r, cmb + cc)] = sV[cc * PITCH_V + j];
        }
        __syncthreads();   // reads of z(t-1) from sV done before overwrite

        // write z(t) -> out + sV z-region
#pragma unroll
        for (int i = 0; i < 4; ++i) {
            int h = hq + 16 * i;
            out[(((size_t)b * Tn + t) * Hn + h) * Nn + col0 + cc2] = zv[i];
            sV[cc2 * PITCH_V + 128 + h] = zv[i];
        }

        grid_barrier(&lsense);   // barriers #2..#65
    }

    grid_barrier(&lsense);       // barrier #66 (even parity)
}

extern "C" void kernel_launch(void* const* d_in, const int* in_sizes, int n_in,
                              void* d_out, int out_size) {
    const float* x     = (const float*)d_in[0];
    const float* z0    = (const float*)d_in[1];
    const float* S     = (const float*)d_in[2];
    const float* aW    = (const float*)d_in[3];
    const float* bW    = (const float*)d_in[4];
    const float* xBias = (const float*)d_in[5];
    const float* zBias = (const float*)d_in[6];
    float* out = (float*)d_out;

    cudaFuncSetAttribute(hs_db_kernel,
                         cudaFuncAttributeMaxDynamicSharedMemorySize, SMEM_BYTES);
    hs_db_kernel<<<NCTAS, NTHREADS, SMEM_BYTES>>>(x, z0, S, aW, bW, xBias, zBias, out);
}